// round 2
// baseline (speedup 1.0000x reference)
#include <cuda_runtime.h>
#include <cuda_bf16.h>

// NCEAverage: out[b,k] = exp(dot(memory[idx'[b,k]], x[b]) / T) / Z
// idx'[b,0] = y[b];  Z = mean(out_unnorm) * N
//
// B=256, K=4096, D=128, N=1e6, T=0.07
// Inputs (metadata order): x f32[256*128], y i32[256], idx i32[256*4096],
//                          memory f32[1e6*128]. Output f32[256*4096].

#define B_SZ 256
#define K_SZ 4096
#define D_SZ 128
#define N_SZ 1000000
#define INV_T (1.0f / 0.07f)

#define SPLIT 8          // gridDim.y
#define WARPS 8          // warps per block
#define KCHUNK (K_SZ / SPLIT)      // 512 k's per block
#define ITERS (KCHUNK / WARPS)     // 64 k's per warp
#define NPART (B_SZ * SPLIT)       // 2048 block partials

__device__ float g_partials[NPART];
__device__ float g_scale;

__global__ __launch_bounds__(WARPS * 32, 8)
void nce_scores_kernel(const float* __restrict__ x,
                       const int* __restrict__ y,
                       const int* __restrict__ idx,
                       const float* __restrict__ memory,
                       float* __restrict__ out) {
    const int b    = blockIdx.x;
    const int lane = threadIdx.x & 31;
    const int warp = threadIdx.x >> 5;
    const int k0   = blockIdx.y * KCHUNK;

    // x row for this b: lane l holds elements [4l, 4l+4)
    const float4 xv = reinterpret_cast<const float4*>(x + b * D_SZ)[lane];

    const int* idx_b = idx + (size_t)b * K_SZ;
    float wsum = 0.0f;

    // each warp: k = k0 + warp + i*WARPS, i in [0, ITERS). Unroll x2 for MLP.
    #pragma unroll 1
    for (int i = 0; i < ITERS; i += 2) {
        const int k1 = k0 + warp + (i    ) * WARPS;
        const int k2 = k0 + warp + (i + 1) * WARPS;

        const int row1 = (k1 == 0) ? y[b] : idx_b[k1];
        const int row2 = idx_b[k2];   // k2 >= 8, never the forced-positive slot

        const float4 w1 = reinterpret_cast<const float4*>(memory + (size_t)row1 * D_SZ)[lane];
        const float4 w2 = reinterpret_cast<const float4*>(memory + (size_t)row2 * D_SZ)[lane];

        float d1 = w1.x * xv.x + w1.y * xv.y + w1.z * xv.z + w1.w * xv.w;
        float d2 = w2.x * xv.x + w2.y * xv.y + w2.z * xv.z + w2.w * xv.w;

        #pragma unroll
        for (int s = 16; s > 0; s >>= 1) {
            d1 += __shfl_xor_sync(0xffffffffu, d1, s);
            d2 += __shfl_xor_sync(0xffffffffu, d2, s);
        }

        if (lane == 0) {
            const float s1 = __expf(d1 * INV_T);
            const float s2 = __expf(d2 * INV_T);
            out[(size_t)b * K_SZ + k1] = s1;
            out[(size_t)b * K_SZ + k2] = s2;
            wsum += s1 + s2;
        }
    }

    // Deterministic block reduce: lane0 of each warp -> smem, thread 0 sums in order.
    __shared__ float ssum[WARPS];
    if (lane == 0) ssum[warp] = wsum;
    __syncthreads();
    if (threadIdx.x == 0) {
        float t = 0.0f;
        #pragma unroll
        for (int w = 0; w < WARPS; w++) t += ssum[w];
        g_partials[blockIdx.y * gridDim.x + blockIdx.x] = t;
    }
}

__global__ void nce_reduce_kernel() {
    __shared__ double sh[256];
    double t = 0.0;
    for (int i = threadIdx.x; i < NPART; i += 256) t += (double)g_partials[i];
    sh[threadIdx.x] = t;
    __syncthreads();
    for (int s = 128; s > 0; s >>= 1) {
        if (threadIdx.x < s) sh[threadIdx.x] += sh[threadIdx.x + s];
        __syncthreads();
    }
    if (threadIdx.x == 0) {
        // Z = (sum / (B*K)) * N ; scale = 1/Z  — all in double to avoid
        // fp32 overflow (sum ~ 1e31, sum*N would be inf in fp32).
        const double sum = sh[0];
        const double scale = ((double)B_SZ * (double)K_SZ) /
                             (sum * (double)N_SZ);
        g_scale = (float)scale;
    }
}

__global__ __launch_bounds__(256)
void nce_norm_kernel(float* __restrict__ out) {
    const float s = g_scale;
    const int i = blockIdx.x * blockDim.x + threadIdx.x;  // over float4s
    float4* o = reinterpret_cast<float4*>(out);
    float4 v = o[i];
    v.x *= s; v.y *= s; v.z *= s; v.w *= s;
    o[i] = v;
}

extern "C" void kernel_launch(void* const* d_in, const int* in_sizes, int n_in,
                              void* d_out, int out_size) {
    const float* x      = (const float*)d_in[0];
    const int*   y      = (const int*)d_in[1];
    const int*   idx    = (const int*)d_in[2];
    const float* memory = (const float*)d_in[3];
    float* out = (float*)d_out;

    dim3 grid1(B_SZ, SPLIT);
    nce_scores_kernel<<<grid1, WARPS * 32>>>(x, y, idx, memory, out);
    nce_reduce_kernel<<<1, 256>>>();
    const int nvec4 = (B_SZ * K_SZ) / 4;   // 262144
    nce_norm_kernel<<<nvec4 / 256, 256>>>(out);
}